// round 5
// baseline (speedup 1.0000x reference)
#include <cuda_runtime.h>
#include <cuda_bf16.h>

// Scratch (device globals; zero-initialized at module load, reset each run
// by the tail block so graph replays are deterministic).
__device__ float g_sV[8192];      // sV = W_next @ V_next   [N]
__device__ float g_pP[8192];      // pi @ P_i               [K]
__device__ float g_pPh[8192];     // pi @ P_hat_i           [K]
__device__ unsigned g_ticket = 0; // work-stealing tile ticket
__device__ unsigned g_done   = 0; // completed-block counter

// Fully fused persistent kernel.
// 1536 tiles of ~128KB: tile t -> type = t % 3 (0:W, 1:P, 2:Ph), idx = t / 3.
//   W tile : rows [idx*8, idx*8+8), warp per row, MLP~8 float4 batches.
//   P tile : 32 rows x 1024 cols, 256 thr x float4, MLP~8, atomicAdd partials.
// The last block to finish (done-counter) runs the epilogue inline, then
// resets all scratch state for the next graph replay.
__global__ __launch_bounds__(256, 4)
void fused_kernel(const float* __restrict__ W,  const float* __restrict__ Vn,
                  const float* __restrict__ P,  const float* __restrict__ Ph,
                  const float* __restrict__ pi, const float* __restrict__ C,
                  const float* __restrict__ L,  const float* __restrict__ U,
                  const float* __restrict__ alpha, float* __restrict__ out,
                  int N, int Nnext, int K, int Prows, int nTiles) {
    __shared__ int s_t;
    __shared__ int s_last;
    const int tid = threadIdx.x;

    // ---------------- matvec phase: work-stealing over tiles ----------------
    for (;;) {
        if (tid == 0) s_t = (int)atomicAdd(&g_ticket, 1u);
        __syncthreads();
        const int t = s_t;
        __syncthreads();              // all threads have read s_t before next write
        if (t >= nTiles) break;

        const int type = t % 3;
        const int idx  = t / 3;

        if (type == 0) {
            // ---- W tile: 8 rows, warp per row ----
            const int warp = tid >> 5;
            const int lane = tid & 31;
            const int row  = idx * 8 + warp;

            const float4* wr = reinterpret_cast<const float4*>(W + (size_t)row * Nnext) + lane;
            const float4* vv = reinterpret_cast<const float4*>(Vn) + lane;
            const int nBatch = Nnext / (32 * 4 * 4);      // 4096/512 = 8

            float acc = 0.0f;
            #pragma unroll 1
            for (int it = 0; it < nBatch; ++it) {
                float4 w0 = __ldg(wr + 0 * 32);
                float4 w1 = __ldg(wr + 1 * 32);
                float4 w2 = __ldg(wr + 2 * 32);
                float4 w3 = __ldg(wr + 3 * 32);
                float4 v0 = __ldg(vv + 0 * 32);
                float4 v1 = __ldg(vv + 1 * 32);
                float4 v2 = __ldg(vv + 2 * 32);
                float4 v3 = __ldg(vv + 3 * 32);
                acc = fmaf(w0.x, v0.x, acc); acc = fmaf(w0.y, v0.y, acc);
                acc = fmaf(w0.z, v0.z, acc); acc = fmaf(w0.w, v0.w, acc);
                acc = fmaf(w1.x, v1.x, acc); acc = fmaf(w1.y, v1.y, acc);
                acc = fmaf(w1.z, v1.z, acc); acc = fmaf(w1.w, v1.w, acc);
                acc = fmaf(w2.x, v2.x, acc); acc = fmaf(w2.y, v2.y, acc);
                acc = fmaf(w2.z, v2.z, acc); acc = fmaf(w2.w, v2.w, acc);
                acc = fmaf(w3.x, v3.x, acc); acc = fmaf(w3.y, v3.y, acc);
                acc = fmaf(w3.z, v3.z, acc); acc = fmaf(w3.w, v3.w, acc);
                wr += 4 * 32;
                vv += 4 * 32;
            }
            #pragma unroll
            for (int o = 16; o > 0; o >>= 1)
                acc += __shfl_down_sync(0xFFFFFFFFu, acc, o);
            if (lane == 0) g_sV[row] = acc;
        } else {
            // ---- P / P_hat tile: 32 rows x 1024 cols ----
            const float* mat = (type == 1) ? P : Ph;
            float* o_        = (type == 1) ? g_pP : g_pPh;

            const int col = (idx & 1) * 1024 + tid * 4;
            const int r0  = (idx >> 1) * 32;

            const float4* m  = reinterpret_cast<const float4*>(mat + (size_t)r0 * K + col);
            const float4* p4 = reinterpret_cast<const float4*>(pi + r0);
            const size_t  s4 = (size_t)K / 4;

            float4 acc = make_float4(0.f, 0.f, 0.f, 0.f);
            #pragma unroll 1
            for (int rr = 0; rr < 32; rr += 8) {
                float4 w0 = __ldg(m + 0 * s4);
                float4 w1 = __ldg(m + 1 * s4);
                float4 w2 = __ldg(m + 2 * s4);
                float4 w3 = __ldg(m + 3 * s4);
                float4 w4 = __ldg(m + 4 * s4);
                float4 w5 = __ldg(m + 5 * s4);
                float4 w6 = __ldg(m + 6 * s4);
                float4 w7 = __ldg(m + 7 * s4);
                float4 pa = __ldg(p4 + 0);
                float4 pb = __ldg(p4 + 1);

                acc.x = fmaf(pa.x, w0.x, acc.x); acc.y = fmaf(pa.x, w0.y, acc.y);
                acc.z = fmaf(pa.x, w0.z, acc.z); acc.w = fmaf(pa.x, w0.w, acc.w);
                acc.x = fmaf(pa.y, w1.x, acc.x); acc.y = fmaf(pa.y, w1.y, acc.y);
                acc.z = fmaf(pa.y, w1.z, acc.z); acc.w = fmaf(pa.y, w1.w, acc.w);
                acc.x = fmaf(pa.z, w2.x, acc.x); acc.y = fmaf(pa.z, w2.y, acc.y);
                acc.z = fmaf(pa.z, w2.z, acc.z); acc.w = fmaf(pa.z, w2.w, acc.w);
                acc.x = fmaf(pa.w, w3.x, acc.x); acc.y = fmaf(pa.w, w3.y, acc.y);
                acc.z = fmaf(pa.w, w3.z, acc.z); acc.w = fmaf(pa.w, w3.w, acc.w);
                acc.x = fmaf(pb.x, w4.x, acc.x); acc.y = fmaf(pb.x, w4.y, acc.y);
                acc.z = fmaf(pb.x, w4.z, acc.z); acc.w = fmaf(pb.x, w4.w, acc.w);
                acc.x = fmaf(pb.y, w5.x, acc.x); acc.y = fmaf(pb.y, w5.y, acc.y);
                acc.z = fmaf(pb.y, w5.z, acc.z); acc.w = fmaf(pb.y, w5.w, acc.w);
                acc.x = fmaf(pb.z, w6.x, acc.x); acc.y = fmaf(pb.z, w6.y, acc.y);
                acc.z = fmaf(pb.z, w6.z, acc.z); acc.w = fmaf(pb.z, w6.w, acc.w);
                acc.x = fmaf(pb.w, w7.x, acc.x); acc.y = fmaf(pb.w, w7.y, acc.y);
                acc.z = fmaf(pb.w, w7.z, acc.z); acc.w = fmaf(pb.w, w7.w, acc.w);

                m  += 8 * s4;
                p4 += 2;
            }
            atomicAdd(&o_[col + 0], acc.x);
            atomicAdd(&o_[col + 1], acc.y);
            atomicAdd(&o_[col + 2], acc.z);
            atomicAdd(&o_[col + 3], acc.w);
        }
        __syncthreads();
    }

    // ---------------- tail-block detection ----------------
    __threadfence();
    if (tid == 0) {
        unsigned d = atomicAdd(&g_done, 1u);
        s_last = (d == gridDim.x - 1);
    }
    __syncthreads();
    if (!s_last) return;

    // ---------------- epilogue (runs in exactly one block) ----------------
    // 256 threads x 16 consecutive neurons each (N <= 4096).
    const int lane = tid & 31, warp = tid >> 5;
    const int base = tid * 16;

    // pass 1: build 16-bit unstable mask + count
    unsigned mask16 = 0;
    #pragma unroll
    for (int j = 0; j < 4; ++j) {
        int n = base + j * 4;
        if (n < N) {
            float4 l = __ldg(reinterpret_cast<const float4*>(L + n));
            float4 u = __ldg(reinterpret_cast<const float4*>(U + n));
            mask16 |= ((l.x < 0.f && u.x > 0.f) ? 1u : 0u) << (j * 4 + 0);
            mask16 |= ((l.y < 0.f && u.y > 0.f) ? 1u : 0u) << (j * 4 + 1);
            mask16 |= ((l.z < 0.f && u.z > 0.f) ? 1u : 0u) << (j * 4 + 2);
            mask16 |= ((l.w < 0.f && u.w > 0.f) ? 1u : 0u) << (j * 4 + 3);
        }
    }
    int cnt = __popc(mask16);

    // block-wide exclusive scan of per-thread counts (8 warps)
    int inc = cnt;
    #pragma unroll
    for (int o = 1; o < 32; o <<= 1) {
        int v = __shfl_up_sync(0xFFFFFFFFu, inc, o);
        if (lane >= o) inc += v;
    }
    __shared__ int wsum[8];
    if (lane == 31) wsum[warp] = inc;
    __syncthreads();
    int k = inc - cnt;
    #pragma unroll
    for (int w = 0; w < 8; ++w) k += (w < warp) ? wsum[w] : 0;

    // pass 2: compute outputs (loads now L1/L2-hot)
    #pragma unroll
    for (int j = 0; j < 4; ++j) {
        int n = base + j * 4;
        if (n >= N) break;
        float4 l = __ldg(reinterpret_cast<const float4*>(L + n));
        float4 u = __ldg(reinterpret_cast<const float4*>(U + n));
        float4 c = __ldg(reinterpret_cast<const float4*>(C + n));
        float4 r;
        float lv[4] = {l.x, l.y, l.z, l.w};
        float uv[4] = {u.x, u.y, u.z, u.w};
        float cv[4] = {c.x, c.y, c.z, c.w};
        float rv[4];
        #pragma unroll
        for (int e = 0; e < 4; ++e) {
            float val;
            if ((mask16 >> (j * 4 + e)) & 1u) {
                if (k < K) {
                    float vhat = g_sV[n + e] - g_pPh[k];
                    float rp   = fmaxf(vhat, 0.0f);
                    float rn   = fmaxf(-vhat, 0.0f);
                    val = rp * uv[e] / (uv[e] - lv[e]) - cv[e]
                          - __ldg(alpha + k) * rn - g_pP[k];
                } else {
                    val = 0.0f;
                }
                ++k;
            } else if (uv[e] <= 0.0f) {
                val = -cv[e];                     // stably deactivated
            } else if (lv[e] >= 0.0f) {
                val = g_sV[n + e] - cv[e];        // stably activated
            } else {
                val = 0.0f;
            }
            rv[e] = val;
        }
        r.x = rv[0]; r.y = rv[1]; r.z = rv[2]; r.w = rv[3];
        *reinterpret_cast<float4*>(out + n) = r;
    }

    // ---------------- reset scratch for next graph replay ----------------
    __syncthreads();
    if (tid == 0) { g_ticket = 0; g_done = 0; }
    for (int i = tid; i < K; i += 256) {
        g_pP[i]  = 0.0f;
        g_pPh[i] = 0.0f;
    }
}

extern "C" void kernel_launch(void* const* d_in, const int* in_sizes, int n_in,
                              void* d_out, int out_size) {
    const float* Vn    = (const float*)d_in[0];   // [N_NEXT]
    const float* W     = (const float*)d_in[1];   // [N_NEXT, N]
    const float* C     = (const float*)d_in[2];   // [N]
    const float* L     = (const float*)d_in[3];   // [N]
    const float* U     = (const float*)d_in[4];   // [N]
    const float* P     = (const float*)d_in[5];   // [P_ROWS, K]
    const float* Ph    = (const float*)d_in[6];   // [P_ROWS, K]
    const float* pi    = (const float*)d_in[7];   // [P_ROWS]
    const float* alpha = (const float*)d_in[8];   // [K]
    float* out = (float*)d_out;

    const int Nnext = in_sizes[0];
    const int N     = in_sizes[2];
    const int Prows = in_sizes[7];
    const int K     = in_sizes[8];

    // 512 W tiles (8 rows each) + 2 * 512 P tiles (32 rows x 1024 cols)
    const int nTiles = N / 8 + 2 * (Prows / 32) * (K / 1024);   // 1536

    const int grid = 152 * 4;   // persistent: 4 CTAs per SM on GB300 (152 SMs)
    fused_kernel<<<grid, 256>>>(W, Vn, P, Ph, pi, C, L, U, alpha, out,
                                N, Nnext, K, Prows, nTiles);
}

// round 6
// speedup vs baseline: 1.0106x; 1.0106x over previous
#include <cuda_runtime.h>
#include <cuda_bf16.h>

// Scratch (device globals; zero-initialized at module load, reset each run
// by the epilogue blocks so graph replays are deterministic).
__device__ float g_sV[8192];      // sV = W_next @ V_next   [N]
__device__ float g_pP[8192];      // pi @ P_i               [K]
__device__ float g_pPh[8192];     // pi @ P_hat_i           [K]
__device__ unsigned g_ticket = 0; // work-stealing tile ticket
__device__ unsigned g_done   = 0; // blocks finished with matvec work
__device__ unsigned g_done2  = 0; // epilogue blocks finished

#define EPI_BLOCKS 32

// Fully fused persistent kernel.
// 1536 tiles of ~128KB: tile t -> type = t % 3 (0:W, 1:P, 2:Ph), idx = t / 3.
//   W tile : rows [idx*8, idx*8+8), warp per row, MLP~8 float4 batches.
//   P tile : 32 rows x 1024 cols, 256 thr x float4, MLP~8, atomicAdd partials.
// The LAST EPI_BLOCKS blocks to run out of tickets spin until all blocks are
// done, then run the epilogue in parallel (one 128-neuron slice each).
__global__ __launch_bounds__(256, 4)
void fused_kernel(const float* __restrict__ W,  const float* __restrict__ Vn,
                  const float* __restrict__ P,  const float* __restrict__ Ph,
                  const float* __restrict__ pi, const float* __restrict__ C,
                  const float* __restrict__ L,  const float* __restrict__ U,
                  const float* __restrict__ alpha, float* __restrict__ out,
                  int N, int Nnext, int K, int Prows, int nTiles) {
    __shared__ int s_t[2];
    __shared__ int s_d;
    const int tid = threadIdx.x;

    // ---------------- matvec phase: work-stealing over tiles ----------------
    if (tid == 0) s_t[0] = (int)atomicAdd(&g_ticket, 1u);
    int parity = 0;
    __syncthreads();

    for (;;) {
        const int t = s_t[parity];
        if (t < nTiles && tid == 0)
            s_t[parity ^ 1] = (int)atomicAdd(&g_ticket, 1u);  // prefetch next ticket
        if (t >= nTiles) break;

        const int type = t % 3;
        const int idx  = t / 3;

        if (type == 0) {
            // ---- W tile: 8 rows, warp per row ----
            const int warp = tid >> 5;
            const int lane = tid & 31;
            const int row  = idx * 8 + warp;

            const float4* wr = reinterpret_cast<const float4*>(W + (size_t)row * Nnext) + lane;
            const float4* vv = reinterpret_cast<const float4*>(Vn) + lane;
            const int nBatch = Nnext / (32 * 4 * 4);      // 4096/512 = 8

            float acc = 0.0f;
            #pragma unroll 1
            for (int it = 0; it < nBatch; ++it) {
                float4 w0 = __ldg(wr + 0 * 32);
                float4 w1 = __ldg(wr + 1 * 32);
                float4 w2 = __ldg(wr + 2 * 32);
                float4 w3 = __ldg(wr + 3 * 32);
                float4 v0 = __ldg(vv + 0 * 32);
                float4 v1 = __ldg(vv + 1 * 32);
                float4 v2 = __ldg(vv + 2 * 32);
                float4 v3 = __ldg(vv + 3 * 32);
                acc = fmaf(w0.x, v0.x, acc); acc = fmaf(w0.y, v0.y, acc);
                acc = fmaf(w0.z, v0.z, acc); acc = fmaf(w0.w, v0.w, acc);
                acc = fmaf(w1.x, v1.x, acc); acc = fmaf(w1.y, v1.y, acc);
                acc = fmaf(w1.z, v1.z, acc); acc = fmaf(w1.w, v1.w, acc);
                acc = fmaf(w2.x, v2.x, acc); acc = fmaf(w2.y, v2.y, acc);
                acc = fmaf(w2.z, v2.z, acc); acc = fmaf(w2.w, v2.w, acc);
                acc = fmaf(w3.x, v3.x, acc); acc = fmaf(w3.y, v3.y, acc);
                acc = fmaf(w3.z, v3.z, acc); acc = fmaf(w3.w, v3.w, acc);
                wr += 4 * 32;
                vv += 4 * 32;
            }
            #pragma unroll
            for (int o = 16; o > 0; o >>= 1)
                acc += __shfl_down_sync(0xFFFFFFFFu, acc, o);
            if (lane == 0) g_sV[row] = acc;
        } else {
            // ---- P / P_hat tile: 32 rows x 1024 cols ----
            const float* mat = (type == 1) ? P : Ph;
            float* o_        = (type == 1) ? g_pP : g_pPh;

            const int col = (idx & 1) * 1024 + tid * 4;
            const int r0  = (idx >> 1) * 32;

            const float4* m  = reinterpret_cast<const float4*>(mat + (size_t)r0 * K + col);
            const float4* p4 = reinterpret_cast<const float4*>(pi + r0);
            const size_t  s4 = (size_t)K / 4;

            float4 acc = make_float4(0.f, 0.f, 0.f, 0.f);
            #pragma unroll 1
            for (int rr = 0; rr < 32; rr += 8) {
                float4 w0 = __ldg(m + 0 * s4);
                float4 w1 = __ldg(m + 1 * s4);
                float4 w2 = __ldg(m + 2 * s4);
                float4 w3 = __ldg(m + 3 * s4);
                float4 w4 = __ldg(m + 4 * s4);
                float4 w5 = __ldg(m + 5 * s4);
                float4 w6 = __ldg(m + 6 * s4);
                float4 w7 = __ldg(m + 7 * s4);
                float4 pa = __ldg(p4 + 0);
                float4 pb = __ldg(p4 + 1);

                acc.x = fmaf(pa.x, w0.x, acc.x); acc.y = fmaf(pa.x, w0.y, acc.y);
                acc.z = fmaf(pa.x, w0.z, acc.z); acc.w = fmaf(pa.x, w0.w, acc.w);
                acc.x = fmaf(pa.y, w1.x, acc.x); acc.y = fmaf(pa.y, w1.y, acc.y);
                acc.z = fmaf(pa.y, w1.z, acc.z); acc.w = fmaf(pa.y, w1.w, acc.w);
                acc.x = fmaf(pa.z, w2.x, acc.x); acc.y = fmaf(pa.z, w2.y, acc.y);
                acc.z = fmaf(pa.z, w2.z, acc.z); acc.w = fmaf(pa.z, w2.w, acc.w);
                acc.x = fmaf(pa.w, w3.x, acc.x); acc.y = fmaf(pa.w, w3.y, acc.y);
                acc.z = fmaf(pa.w, w3.z, acc.z); acc.w = fmaf(pa.w, w3.w, acc.w);
                acc.x = fmaf(pb.x, w4.x, acc.x); acc.y = fmaf(pb.x, w4.y, acc.y);
                acc.z = fmaf(pb.x, w4.z, acc.z); acc.w = fmaf(pb.x, w4.w, acc.w);
                acc.x = fmaf(pb.y, w5.x, acc.x); acc.y = fmaf(pb.y, w5.y, acc.y);
                acc.z = fmaf(pb.y, w5.z, acc.z); acc.w = fmaf(pb.y, w5.w, acc.w);
                acc.x = fmaf(pb.z, w6.x, acc.x); acc.y = fmaf(pb.z, w6.y, acc.y);
                acc.z = fmaf(pb.z, w6.z, acc.z); acc.w = fmaf(pb.z, w6.w, acc.w);
                acc.x = fmaf(pb.w, w7.x, acc.x); acc.y = fmaf(pb.w, w7.y, acc.y);
                acc.z = fmaf(pb.w, w7.z, acc.z); acc.w = fmaf(pb.w, w7.w, acc.w);

                m  += 8 * s4;
                p4 += 2;
            }
            atomicAdd(&o_[col + 0], acc.x);
            atomicAdd(&o_[col + 1], acc.y);
            atomicAdd(&o_[col + 2], acc.z);
            atomicAdd(&o_[col + 3], acc.w);
        }
        __syncthreads();
        parity ^= 1;
    }

    // ---------------- tail detection: last EPI_BLOCKS run epilogue ----------
    __threadfence();
    if (tid == 0) {
        unsigned d = atomicAdd(&g_done, 1u);
        s_d = (int)d;
    }
    __syncthreads();
    const int G = (int)gridDim.x;
    if (s_d < G - EPI_BLOCKS) return;
    const int slice = s_d - (G - EPI_BLOCKS);    // [0, EPI_BLOCKS)

    // wait for ALL blocks to finish their tiles
    if (tid == 0) {
        while (atomicAdd(&g_done, 0u) < (unsigned)G) __nanosleep(64);
    }
    __syncthreads();
    __threadfence();

    // ---------------- parallel epilogue: one slice per block ----------------
    const int sliceLen   = (N + EPI_BLOCKS - 1) / EPI_BLOCKS;   // 128 for N=4096
    const int sliceStart = slice * sliceLen;
    const int lane = tid & 31, warp = tid >> 5;

    // rank offset: count unstable in [0, sliceStart), 256 threads parallel
    int pre = 0;
    for (int i = tid; i < sliceStart; i += 256) {
        float li = __ldg(L + i), ui = __ldg(U + i);
        pre += (li < 0.0f && ui > 0.0f);
    }
    #pragma unroll
    for (int o = 16; o > 0; o >>= 1)
        pre += __shfl_down_sync(0xFFFFFFFFu, pre, o);
    __shared__ int wsum[8];
    __shared__ int wcnt[8];
    if (lane == 0) wsum[warp] = pre;
    if (tid < 8) wcnt[tid] = 0;
    __syncthreads();

    // own slice: thread t < sliceLen handles neuron sliceStart + t
    const int n = sliceStart + tid;
    float l = 0.f, u = 0.f, c = 0.f;
    bool un = false;
    const bool active = (tid < sliceLen) && (n < N);
    if (active) {
        l = __ldg(L + n); u = __ldg(U + n); c = __ldg(C + n);
        un = (l < 0.0f) && (u > 0.0f);
    }
    unsigned bm = __ballot_sync(0xFFFFFFFFu, un);
    int before = __popc(bm & ((1u << lane) - 1u));
    if (lane == 0 && warp < 8) wcnt[warp] = __popc(bm);
    __syncthreads();

    int prefix = 0;
    #pragma unroll
    for (int w = 0; w < 8; ++w) prefix += wsum[w];
    int woff = 0, totalCnt = 0;
    #pragma unroll
    for (int w = 0; w < 8; ++w) {
        woff     += (w < warp) ? wcnt[w] : 0;
        totalCnt += wcnt[w];
    }
    const int k = prefix + woff + before;

    if (active) {
        float val;
        if (un) {
            if (k < K) {
                float vhat = g_sV[n] - g_pPh[k];
                float rp   = fmaxf(vhat, 0.0f);
                float rn   = fmaxf(-vhat, 0.0f);
                val = rp * u / (u - l) - c - __ldg(alpha + k) * rn - g_pP[k];
            } else {
                val = 0.0f;
            }
        } else if (u <= 0.0f) {
            val = -c;                  // stably deactivated
        } else if (l >= 0.0f) {
            val = g_sV[n] - c;         // stably activated
        } else {
            val = 0.0f;
        }
        out[n] = val;
    }

    // ---------------- reset scratch for next graph replay -------------------
    __syncthreads();
    // zero the rank range this block consumed (last slice zeroes through K,
    // covering any ranks never consumed)
    const int zEnd = (slice == EPI_BLOCKS - 1) ? K : (prefix + totalCnt);
    for (int i = prefix + tid; i < zEnd; i += 256) {
        g_pP[i]  = 0.0f;
        g_pPh[i] = 0.0f;
    }
    __threadfence();
    if (tid == 0) {
        unsigned d2 = atomicAdd(&g_done2, 1u);
        if (d2 == EPI_BLOCKS - 1) {   // very last epilogue block resets counters
            g_ticket = 0;
            g_done   = 0;
            g_done2  = 0;
            __threadfence();
        }
    }
}

extern "C" void kernel_launch(void* const* d_in, const int* in_sizes, int n_in,
                              void* d_out, int out_size) {
    const float* Vn    = (const float*)d_in[0];   // [N_NEXT]
    const float* W     = (const float*)d_in[1];   // [N_NEXT, N]
    const float* C     = (const float*)d_in[2];   // [N]
    const float* L     = (const float*)d_in[3];   // [N]
    const float* U     = (const float*)d_in[4];   // [N]
    const float* P     = (const float*)d_in[5];   // [P_ROWS, K]
    const float* Ph    = (const float*)d_in[6];   // [P_ROWS, K]
    const float* pi    = (const float*)d_in[7];   // [P_ROWS]
    const float* alpha = (const float*)d_in[8];   // [K]
    float* out = (float*)d_out;

    const int Nnext = in_sizes[0];
    const int N     = in_sizes[2];
    const int Prows = in_sizes[7];
    const int K     = in_sizes[8];

    // 512 W tiles (8 rows each) + 2 * 512 P tiles (32 rows x 1024 cols)
    const int nTiles = N / 8 + 2 * (Prows / 32) * (K / 1024);   // 1536

    const int grid = 152 * 4;   // persistent, work-stealing; GB300 has 152 SMs
    fused_kernel<<<grid, 256>>>(W, Vn, P, Ph, pi, C, L, U, alpha, out,
                                N, Nnext, K, Prows, nTiles);
}

// round 7
// speedup vs baseline: 1.1341x; 1.1222x over previous
#include <cuda_runtime.h>
#include <cuda_bf16.h>

// Scratch (device globals; zero-initialized at module load, reset each run
// by the epilogue blocks so graph replays are deterministic).
__device__ float g_sV[8192];      // sV = W_next @ V_next   [N]
__device__ float g_pP[8192];      // pi @ P_i               [K]
__device__ float g_pPh[8192];     // pi @ P_hat_i           [K]
__device__ unsigned g_done  = 0;  // blocks finished with matvec work
__device__ unsigned g_done2 = 0;  // epilogue blocks finished

#define EPI_BLOCKS 32

// Single-launch fused kernel, static balanced tiling (R4 matvec structure).
// Grid = 512 blocks x 256 threads. 1536 tiles of ~128KB:
//   tile t -> type = t % 3 (0:W, 1:P, 2:Ph), idx = t / 3.
//   Block b handles tiles {b, b+512, b+1024}; 512 % 3 == 2 so every block
//   gets exactly one tile of each type -> identical 384KB of traffic.
// Blocks 0..31 additionally run the epilogue: they precompute their slice's
// unstable-rank prefix right after their own matvec work (hidden in the
// block-finish spread), spin until all blocks are done, then do the
// elementwise output writes from L2-hot scratch.
__global__ __launch_bounds__(256, 4)
void fused_kernel(const float* __restrict__ W,  const float* __restrict__ Vn,
                  const float* __restrict__ P,  const float* __restrict__ Ph,
                  const float* __restrict__ pi, const float* __restrict__ C,
                  const float* __restrict__ L,  const float* __restrict__ U,
                  const float* __restrict__ alpha, float* __restrict__ out,
                  int N, int Nnext, int K, int Prows, int G) {
    const int tid = threadIdx.x;
    const int b   = blockIdx.x;

    // ---------------- matvec phase: 3 static tiles ----------------
    #pragma unroll 1
    for (int i = 0; i < 3; ++i) {
        const int t    = b + G * i;
        const int type = t % 3;
        const int idx  = t / 3;

        if (type == 0) {
            // ---- W tile: 8 rows, warp per row ----
            const int warp = tid >> 5;
            const int lane = tid & 31;
            const int row  = idx * 8 + warp;

            const float4* wr = reinterpret_cast<const float4*>(W + (size_t)row * Nnext) + lane;
            const float4* vv = reinterpret_cast<const float4*>(Vn) + lane;
            const int nBatch = Nnext / (32 * 4 * 4);      // 4096/512 = 8

            float acc = 0.0f;
            #pragma unroll 1
            for (int it = 0; it < nBatch; ++it) {
                float4 w0 = __ldg(wr + 0 * 32);
                float4 w1 = __ldg(wr + 1 * 32);
                float4 w2 = __ldg(wr + 2 * 32);
                float4 w3 = __ldg(wr + 3 * 32);
                float4 v0 = __ldg(vv + 0 * 32);
                float4 v1 = __ldg(vv + 1 * 32);
                float4 v2 = __ldg(vv + 2 * 32);
                float4 v3 = __ldg(vv + 3 * 32);
                acc = fmaf(w0.x, v0.x, acc); acc = fmaf(w0.y, v0.y, acc);
                acc = fmaf(w0.z, v0.z, acc); acc = fmaf(w0.w, v0.w, acc);
                acc = fmaf(w1.x, v1.x, acc); acc = fmaf(w1.y, v1.y, acc);
                acc = fmaf(w1.z, v1.z, acc); acc = fmaf(w1.w, v1.w, acc);
                acc = fmaf(w2.x, v2.x, acc); acc = fmaf(w2.y, v2.y, acc);
                acc = fmaf(w2.z, v2.z, acc); acc = fmaf(w2.w, v2.w, acc);
                acc = fmaf(w3.x, v3.x, acc); acc = fmaf(w3.y, v3.y, acc);
                acc = fmaf(w3.z, v3.z, acc); acc = fmaf(w3.w, v3.w, acc);
                wr += 4 * 32;
                vv += 4 * 32;
            }
            #pragma unroll
            for (int o = 16; o > 0; o >>= 1)
                acc += __shfl_down_sync(0xFFFFFFFFu, acc, o);
            if (lane == 0) g_sV[row] = acc;
        } else {
            // ---- P / P_hat tile: 32 rows x 1024 cols ----
            const float* mat = (type == 1) ? P : Ph;
            float* o_        = (type == 1) ? g_pP : g_pPh;

            const int col = (idx & 1) * 1024 + tid * 4;
            const int r0  = (idx >> 1) * 32;

            const float4* m  = reinterpret_cast<const float4*>(mat + (size_t)r0 * K + col);
            const float4* p4 = reinterpret_cast<const float4*>(pi + r0);
            const size_t  s4 = (size_t)K / 4;

            float4 acc = make_float4(0.f, 0.f, 0.f, 0.f);
            #pragma unroll 1
            for (int rr = 0; rr < 32; rr += 8) {
                float4 w0 = __ldg(m + 0 * s4);
                float4 w1 = __ldg(m + 1 * s4);
                float4 w2 = __ldg(m + 2 * s4);
                float4 w3 = __ldg(m + 3 * s4);
                float4 w4 = __ldg(m + 4 * s4);
                float4 w5 = __ldg(m + 5 * s4);
                float4 w6 = __ldg(m + 6 * s4);
                float4 w7 = __ldg(m + 7 * s4);
                float4 pa = __ldg(p4 + 0);
                float4 pb = __ldg(p4 + 1);

                acc.x = fmaf(pa.x, w0.x, acc.x); acc.y = fmaf(pa.x, w0.y, acc.y);
                acc.z = fmaf(pa.x, w0.z, acc.z); acc.w = fmaf(pa.x, w0.w, acc.w);
                acc.x = fmaf(pa.y, w1.x, acc.x); acc.y = fmaf(pa.y, w1.y, acc.y);
                acc.z = fmaf(pa.y, w1.z, acc.z); acc.w = fmaf(pa.y, w1.w, acc.w);
                acc.x = fmaf(pa.z, w2.x, acc.x); acc.y = fmaf(pa.z, w2.y, acc.y);
                acc.z = fmaf(pa.z, w2.z, acc.z); acc.w = fmaf(pa.z, w2.w, acc.w);
                acc.x = fmaf(pa.w, w3.x, acc.x); acc.y = fmaf(pa.w, w3.y, acc.y);
                acc.z = fmaf(pa.w, w3.z, acc.z); acc.w = fmaf(pa.w, w3.w, acc.w);
                acc.x = fmaf(pb.x, w4.x, acc.x); acc.y = fmaf(pb.x, w4.y, acc.y);
                acc.z = fmaf(pb.x, w4.z, acc.z); acc.w = fmaf(pb.x, w4.w, acc.w);
                acc.x = fmaf(pb.y, w5.x, acc.x); acc.y = fmaf(pb.y, w5.y, acc.y);
                acc.z = fmaf(pb.y, w5.z, acc.z); acc.w = fmaf(pb.y, w5.w, acc.w);
                acc.x = fmaf(pb.z, w6.x, acc.x); acc.y = fmaf(pb.z, w6.y, acc.y);
                acc.z = fmaf(pb.z, w6.z, acc.z); acc.w = fmaf(pb.z, w6.w, acc.w);
                acc.x = fmaf(pb.w, w7.x, acc.x); acc.y = fmaf(pb.w, w7.y, acc.y);
                acc.z = fmaf(pb.w, w7.z, acc.z); acc.w = fmaf(pb.w, w7.w, acc.w);

                m  += 8 * s4;
                p4 += 2;
            }
            atomicAdd(&o_[col + 0], acc.x);
            atomicAdd(&o_[col + 1], acc.y);
            atomicAdd(&o_[col + 2], acc.z);
            atomicAdd(&o_[col + 3], acc.w);
        }
    }

    // ---------------- signal matvec completion ----------------
    __threadfence();
    if (b >= EPI_BLOCKS) {
        if (tid == 0) atomicAdd(&g_done, 1u);
        return;
    }
    if (tid == 0) atomicAdd(&g_done, 1u);

    // ======== epilogue blocks (b in [0, EPI_BLOCKS)) ========
    // Rank precomputation depends only on L/U: do it NOW, while other blocks
    // are still streaming matvec traffic -> hidden in the finish spread.
    const int sliceLen   = (N + EPI_BLOCKS - 1) / EPI_BLOCKS;   // 128 for N=4096
    const int sliceStart = b * sliceLen;
    const int lane = tid & 31, warp = tid >> 5;

    // count unstable in [0, sliceStart)
    int pre = 0;
    for (int i = tid; i < sliceStart; i += 256) {
        float li = __ldg(L + i), ui = __ldg(U + i);
        pre += (li < 0.0f && ui > 0.0f);
    }
    #pragma unroll
    for (int o = 16; o > 0; o >>= 1)
        pre += __shfl_down_sync(0xFFFFFFFFu, pre, o);
    __shared__ int wsum[8];
    __shared__ int wcnt[8];
    if (lane == 0) wsum[warp] = pre;
    if (tid < 8) wcnt[tid] = 0;
    __syncthreads();

    // own slice mask (thread tid < sliceLen handles neuron sliceStart + tid)
    const int n = sliceStart + tid;
    float l = 0.f, u = 0.f, c = 0.f;
    bool un = false;
    const bool active = (tid < sliceLen) && (n < N);
    if (active) {
        l = __ldg(L + n); u = __ldg(U + n); c = __ldg(C + n);
        un = (l < 0.0f) && (u > 0.0f);
    }
    unsigned bm = __ballot_sync(0xFFFFFFFFu, un);
    int before = __popc(bm & ((1u << lane) - 1u));
    if (lane == 0) wcnt[warp] = __popc(bm);
    __syncthreads();

    int prefix = 0;
    #pragma unroll
    for (int w = 0; w < 8; ++w) prefix += wsum[w];
    int woff = 0, totalCnt = 0;
    #pragma unroll
    for (int w = 0; w < 8; ++w) {
        woff     += (w < warp) ? wcnt[w] : 0;
        totalCnt += wcnt[w];
    }
    const int k = prefix + woff + before;
    float a_k = 0.0f;
    if (active && un && k < K) a_k = __ldg(alpha + k);

    // ---------------- wait for ALL blocks to finish matvec ----------------
    if (tid == 0) {
        while (atomicAdd(&g_done, 0u) < (unsigned)G) __nanosleep(64);
    }
    __syncthreads();
    __threadfence();

    // ---------------- elementwise epilogue (L2-hot) ----------------
    if (active) {
        float val;
        if (un) {
            if (k < K) {
                float vhat = g_sV[n] - g_pPh[k];
                float rp   = fmaxf(vhat, 0.0f);
                float rn   = fmaxf(-vhat, 0.0f);
                val = rp * u / (u - l) - c - a_k * rn - g_pP[k];
            } else {
                val = 0.0f;
            }
        } else if (u <= 0.0f) {
            val = -c;                  // stably deactivated
        } else if (l >= 0.0f) {
            val = g_sV[n] - c;         // stably activated
        } else {
            val = 0.0f;
        }
        out[n] = val;
    }

    // ---------------- reset scratch for next graph replay ----------------
    __syncthreads();
    const int zEnd = (b == EPI_BLOCKS - 1) ? K : (prefix + totalCnt);
    for (int i = prefix + tid; i < zEnd; i += 256) {
        g_pP[i]  = 0.0f;
        g_pPh[i] = 0.0f;
    }
    __threadfence();
    if (tid == 0) {
        unsigned d2 = atomicAdd(&g_done2, 1u);
        if (d2 == EPI_BLOCKS - 1) {   // very last epilogue block resets counters
            g_done  = 0;
            g_done2 = 0;
            __threadfence();
        }
    }
}

extern "C" void kernel_launch(void* const* d_in, const int* in_sizes, int n_in,
                              void* d_out, int out_size) {
    const float* Vn    = (const float*)d_in[0];   // [N_NEXT]
    const float* W     = (const float*)d_in[1];   // [N_NEXT, N]
    const float* C     = (const float*)d_in[2];   // [N]
    const float* L     = (const float*)d_in[3];   // [N]
    const float* U     = (const float*)d_in[4];   // [N]
    const float* P     = (const float*)d_in[5];   // [P_ROWS, K]
    const float* Ph    = (const float*)d_in[6];   // [P_ROWS, K]
    const float* pi    = (const float*)d_in[7];   // [P_ROWS]
    const float* alpha = (const float*)d_in[8];   // [K]
    float* out = (float*)d_out;

    const int Nnext = in_sizes[0];
    const int N     = in_sizes[2];
    const int Prows = in_sizes[7];
    const int K     = in_sizes[8];

    const int G = 512;   // N/8 W tiles; (Prows/32)*(K/1024) P tiles each type

    fused_kernel<<<G, 256>>>(W, Vn, P, Ph, pi, C, L, U, alpha, out,
                             N, Nnext, K, Prows, G);
}